// round 9
// baseline (speedup 1.0000x reference)
#include <cuda_runtime.h>
#include <cuda_fp16.h>

// GaussianSoftmax: X[8,4096,16], sigma[1] -> softmax(exp(exp(-sqdist/sigma)), axis=2) [8,4096,4096]
//
// R9: h lives in REGISTERS (16 tiles x 2 rows of half2 = 32 regs, tile loop fully
// unrolled) -> no 64KB h smem, no h STS/LDS, no phase-2 staging loop. T=512, RR=8,
// thread = 2 rows x 2 cols. Freed smem funds a 4-deep cp.async.bulk pipeline
// (distance-2 prefetch, 4 mbarriers, tid0-only waits). exp(g) computed as
// 2^(2^(e + log2(log2e))) -- the g*L2E mul folded into the exponent constant.
// Final: per-thread normalize + coalesced streaming STG.64.

#define BB 8
#define NN 4096
#define FF 16
#define RR 8
#define TT 512
#define JT 256
#define NT (NN / JT)
#define L2E  1.4426950408889634f
#define C528 0.5287663729448977f   // log2(log2(e))

typedef unsigned long long ull;

__device__ float g_sqc[BB * NN];         // cexp * ||x_j||^2
__device__ float g_xt[BB * FF * NN];     // [b][fp][j] float2: b*65536 + fp*8192 + j*2

// smem byte offsets (4 pipeline stages)
#define XTP_OFF  0
#define XTP_BUF  16384                   // 8 fp-rows x 2048B
#define SQJ_OFF  (XTP_OFF + 4 * XTP_BUF) // 4 x 1024
#define MBAR_OFF (SQJ_OFF + 4096)        // 4 x 8
#define PART_OFF (MBAR_OFF + 32)         // 16 warps x 2 floats
#define INV_OFF  (PART_OFF + 128)        // 8 floats
#define SMEM_TOTAL (INV_OFF + 64)        // ~69.8 KB

__device__ __forceinline__ ull ffma2(ull a, ull b, ull c) {
    ull d; asm("fma.rn.f32x2 %0, %1, %2, %3;" : "=l"(d) : "l"(a), "l"(b), "l"(c)); return d;
}
__device__ __forceinline__ float2 upk(ull v) {
    float2 r; asm("mov.b64 {%0, %1}, %2;" : "=f"(r.x), "=f"(r.y) : "l"(v)); return r;
}
__device__ __forceinline__ float ex2f(float x) {
    float r; asm("ex2.approx.f32 %0, %1;" : "=f"(r) : "f"(x)); return r;
}
__device__ __forceinline__ unsigned pkh2(float a, float b) {
    __half2 h = __floats2half2_rn(a, b);
    return *reinterpret_cast<unsigned*>(&h);
}
__device__ __forceinline__ void stcs2(float* p, float a, float b) {
    asm volatile("st.global.cs.v2.f32 [%0], {%1, %2};"
                 :: "l"(p), "f"(a), "f"(b) : "memory");
}
__device__ __forceinline__ void mbar_init(unsigned mbar, unsigned cnt) {
    asm volatile("mbarrier.init.shared.b64 [%0], %1;" :: "r"(mbar), "r"(cnt) : "memory");
}
__device__ __forceinline__ void mbar_expect_tx(unsigned mbar, unsigned tx) {
    asm volatile("mbarrier.arrive.expect_tx.shared.b64 _, [%0], %1;"
                 :: "r"(mbar), "r"(tx) : "memory");
}
__device__ __forceinline__ void bulk_g2s(unsigned dst, const void* src,
                                         unsigned bytes, unsigned mbar) {
    asm volatile("cp.async.bulk.shared::cta.global.mbarrier::complete_tx::bytes "
                 "[%0], [%1], %2, [%3];"
                 :: "r"(dst), "l"(src), "r"(bytes), "r"(mbar) : "memory");
}
__device__ __forceinline__ void mbar_wait(unsigned mbar, unsigned parity) {
    unsigned done;
    asm volatile(
        "{\n\t.reg .pred p;\n\t"
        "mbarrier.try_wait.parity.acquire.cta.shared::cta.b64 p, [%1], %2;\n\t"
        "selp.b32 %0, 1, 0, p;\n\t}"
        : "=r"(done) : "r"(mbar), "r"(parity) : "memory");
    if (!done) {
        asm volatile(
            "{\n\t.reg .pred P1;\n\t"
            "WL_%=:\n\t"
            "mbarrier.try_wait.parity.acquire.cta.shared::cta.b64 P1, [%0], %1, 0x989680;\n\t"
            "@P1 bra.uni WD_%=;\n\t"
            "bra.uni WL_%=;\n\t"
            "WD_%=:\n\t}"
            :: "r"(mbar), "r"(parity) : "memory");
    }
}

// ---- pre-kernel: transpose X into f-pair rows + cexp*||x_j||^2 ----
__global__ void __launch_bounds__(256)
prep_kernel(const float* __restrict__ X, const float* __restrict__ sigma) {
    int idx = blockIdx.x * 256 + threadIdx.x;          // b*4096 + j
    int b = idx >> 12, j = idx & 4095;
    const float4* p = reinterpret_cast<const float4*>(X) + (size_t)idx * 4;
    float s = 0.f;
    float2* xtb = reinterpret_cast<float2*>(&g_xt[b * 65536]) + j;
    #pragma unroll
    for (int q = 0; q < 4; ++q) {
        float4 v = p[q];
        s += v.x * v.x + v.y * v.y + v.z * v.z + v.w * v.w;
        xtb[(2 * q + 0) * 4096] = make_float2(v.x, v.y);
        xtb[(2 * q + 1) * 4096] = make_float2(v.z, v.w);
    }
    g_sqc[idx] = (-L2E / sigma[0]) * s;
}

__global__ void __launch_bounds__(TT, 1)
GaussianSoftmax_67714454389333_kernel(const float* __restrict__ X,
                                      const float* __restrict__ sigma,
                                      float* __restrict__ out) {
    extern __shared__ char smem_raw[];
    unsigned su;
    asm("{ .reg .u64 t; cvta.to.shared.u64 t, %1; cvt.u32.u64 %0, t; }"
        : "=r"(su) : "l"(smem_raw));

    const int tid = threadIdx.x;
    const int b = blockIdx.y;
    const int i0 = blockIdx.x * RR;
    const int rgrp = tid >> 7;             // 0..3 -> rows rgrp*2, rgrp*2+1
    const int jq = (tid & 127) * 2;        // my 2 cols within tile

    const float* Xb = X + (size_t)b * NN * FF;

    const float sg = sigma[0];
    const float cexp = -L2E / sg;
    const float CM2s = -2.0f * cexp;

    // ---- xq: f-paired xi in regs (2 rows x 8 fpairs) + sic = cexp*sqi + C528 ----
    ull xq[8][2];
    float sic[2];
    #pragma unroll
    for (int r = 0; r < 2; ++r) {
        float s = 0.f;
        #pragma unroll
        for (int fp = 0; fp < 8; ++fp) {
            float2 v = *reinterpret_cast<const float2*>(
                &Xb[(size_t)(i0 + rgrp * 2 + r) * FF + fp * 2]);
            s = fmaf(v.x, v.x, s);
            s = fmaf(v.y, v.y, s);
            xq[fp][r] = *reinterpret_cast<const ull*>(&v);
        }
        sic[r] = fmaf(cexp, s, C528);
    }

    // ---- mbarrier setup + prologue copies (tiles 0,1) ----
    const float* xtB = &g_xt[b * 65536];
    const float* sqB = &g_sqc[b * NN];
    if (tid == 0) {
        #pragma unroll
        for (int m = 0; m < 4; ++m) mbar_init(su + MBAR_OFF + m * 8, 1);
        asm volatile("fence.proxy.async.shared::cta;" ::: "memory");
    }
    __syncthreads();
    if (tid == 0) {
        #pragma unroll
        for (int t0 = 0; t0 < 2; ++t0) {
            unsigned mb = su + MBAR_OFF + t0 * 8;
            mbar_expect_tx(mb, 8 * 2048 + 1024);
            #pragma unroll
            for (int fp = 0; fp < 8; ++fp)
                bulk_g2s(su + XTP_OFF + t0 * XTP_BUF + fp * 2048,
                         xtB + fp * 8192 + t0 * (JT * 2), 2048, mb);
            bulk_g2s(su + SQJ_OFF + t0 * 1024, sqB + t0 * JT, 1024, mb);
        }
    }

    float rsum[2] = {0.f, 0.f};
    unsigned hreg[NT][2];     // half2 per (tile, row) -- fully unrolled => registers

    // ---- main loop: 16 tiles, 4-stage pipeline, distance-2 prefetch ----
    #pragma unroll
    for (int t = 0; t < NT; ++t) {
        if (tid == 0) mbar_wait(su + MBAR_OFF + (t & 3) * 8, (t >> 2) & 1);
        __syncthreads();   // tile t visible to all; compute t-1 done by all

        if (t + 2 < NT && tid == 0) {
            int buf = (t + 2) & 3;
            unsigned mb = su + MBAR_OFF + buf * 8;
            mbar_expect_tx(mb, 8 * 2048 + 1024);
            const float* src = xtB + (t + 2) * (JT * 2);
            #pragma unroll
            for (int fp = 0; fp < 8; ++fp)
                bulk_g2s(su + XTP_OFF + buf * XTP_BUF + fp * 2048,
                         src + fp * 8192, 2048, mb);
            bulk_g2s(su + SQJ_OFF + buf * 1024, sqB + (t + 2) * JT, 1024, mb);
        }

        // dot products: 2 rows x 2 cols, f-paired lanes
        const char* xbuf = smem_raw + XTP_OFF + (t & 3) * XTP_BUF;
        ull acc00 = 0, acc01 = 0, acc10 = 0, acc11 = 0;
        #pragma unroll
        for (int fp = 0; fp < 8; ++fp) {
            ulonglong2 xj = *reinterpret_cast<const ulonglong2*>(
                xbuf + fp * 2048 + jq * 8);
            acc00 = ffma2(xj.x, xq[fp][0], acc00);
            acc01 = ffma2(xj.y, xq[fp][0], acc01);
            acc10 = ffma2(xj.x, xq[fp][1], acc10);
            acc11 = ffma2(xj.y, xq[fp][1], acc11);
        }

        // epilogue: e = CM2s*dot + sic + sj ; h = 2^(2^e)
        float2 sj = *reinterpret_cast<const float2*>(
            smem_raw + SQJ_OFF + (t & 3) * 1024 + jq * 4);
        {
            float2 a0 = upk(acc00), a1 = upk(acc01);
            float e0 = fmaf(CM2s, a0.x + a0.y, sic[0] + sj.x);
            float e1 = fmaf(CM2s, a1.x + a1.y, sic[0] + sj.y);
            float h0 = ex2f(ex2f(e0));
            float h1 = ex2f(ex2f(e1));
            rsum[0] += h0 + h1;
            hreg[t][0] = pkh2(h0, h1);
        }
        {
            float2 a0 = upk(acc10), a1 = upk(acc11);
            float e0 = fmaf(CM2s, a0.x + a0.y, sic[1] + sj.x);
            float e1 = fmaf(CM2s, a1.x + a1.y, sic[1] + sj.y);
            float h0 = ex2f(ex2f(e0));
            float h1 = ex2f(ex2f(e1));
            rsum[1] += h0 + h1;
            hreg[t][1] = pkh2(h0, h1);
        }
    }

    // ---- row-sum reduction: warp partials -> 8 row inverses ----
    float* part = reinterpret_cast<float*>(smem_raw + PART_OFF);   // [16 warps][2]
    #pragma unroll
    for (int r = 0; r < 2; ++r) {
        float v = rsum[r];
        v += __shfl_xor_sync(0xffffffffu, v, 16);
        v += __shfl_xor_sync(0xffffffffu, v, 8);
        v += __shfl_xor_sync(0xffffffffu, v, 4);
        v += __shfl_xor_sync(0xffffffffu, v, 2);
        v += __shfl_xor_sync(0xffffffffu, v, 1);
        if ((tid & 31) == 0) part[(tid >> 5) * 2 + r] = v;
    }
    __syncthreads();
    float* invp = reinterpret_cast<float*>(smem_raw + INV_OFF);
    if (tid < RR) {
        int wg = (tid >> 1) * 4, rl = tid & 1;     // row tid: rgrp=tid>>1
        float s = part[(wg + 0) * 2 + rl] + part[(wg + 1) * 2 + rl] +
                  part[(wg + 2) * 2 + rl] + part[(wg + 3) * 2 + rl];
        invp[tid] = 1.0f / s;
    }
    __syncthreads();

    const float inv0 = invp[rgrp * 2 + 0];
    const float inv1 = invp[rgrp * 2 + 1];

    // ---- normalize from registers + coalesced streaming STG.64 ----
    float* o0 = out + ((size_t)b * NN + i0 + rgrp * 2) * NN + jq;
    float* o1 = o0 + NN;
    #pragma unroll
    for (int t = 0; t < NT; ++t) {
        float2 f0 = __half22float2(*reinterpret_cast<__half2*>(&hreg[t][0]));
        float2 f1 = __half22float2(*reinterpret_cast<__half2*>(&hreg[t][1]));
        stcs2(o0 + t * JT, f0.x * inv0, f0.y * inv0);
        stcs2(o1 + t * JT, f1.x * inv1, f1.y * inv1);
    }
}

extern "C" void kernel_launch(void* const* d_in, const int* in_sizes, int n_in,
                              void* d_out, int out_size) {
    const float* X = (const float*)d_in[0];
    const float* sigma = (const float*)d_in[1];
    float* out = (float*)d_out;

    prep_kernel<<<BB * NN / 256, 256>>>(X, sigma);

    cudaFuncSetAttribute(GaussianSoftmax_67714454389333_kernel,
                         cudaFuncAttributeMaxDynamicSharedMemorySize, SMEM_TOTAL);
    dim3 grid(NN / RR, BB);   // (512, 8)
    GaussianSoftmax_67714454389333_kernel<<<grid, TT, SMEM_TOTAL>>>(X, sigma, out);
}

// round 10
// speedup vs baseline: 1.5349x; 1.5349x over previous
#include <cuda_runtime.h>
#include <cuda_fp16.h>

// GaussianSoftmax: X[8,4096,16], sigma[1] -> softmax(exp(exp(-sqdist/sigma)), axis=2) [8,4096,4096]
//
// R10: BARRIER-FREE mainloop. xj read directly from L2-resident pre-transposed
// g_xt via coalesced LDG.64 (no smem x-tiles, no mbarriers, no per-tile syncs).
// T=128, RR=8, thread = ALL 8 rows x 2 cols (cols tid, tid+128 per k-step):
// xq = 8fp x 8r packed float2 = 128 regs (legal: launch_bounds(128,2) -> 256-reg cap,
// 2 CTAs/SM for phase overlap). xj L1 cost 8B/elem (halved vs R8).
// h = 2^(2^(e + log2log2e)) kept fp16 in smem (64KB); 3 total __syncthreads per CTA.

#define BB 8
#define NN 4096
#define FF 16
#define RR 8
#define TT 128
#define NK 16                     // k-steps of 256 cols
#define L2E  1.4426950408889634f
#define C528 0.5287663729448977f  // log2(log2(e))

typedef unsigned long long ull;

__device__ float g_sqc[BB * NN];      // cexp * ||x_j||^2
__device__ float g_xt[BB * FF * NN];  // [b][fp][j] float2: ull index b*32768 + fp*4096 + j

// smem: hbuf uint[8][2048] = 64KB, then part[4][8], inv[8]
#define HBUF_OFF 0
#define PART_OFF 65536
#define INV_OFF  (PART_OFF + 128)
#define SMEM_TOTAL (INV_OFF + 32)

__device__ __forceinline__ ull ffma2(ull a, ull b, ull c) {
    ull d; asm("fma.rn.f32x2 %0, %1, %2, %3;" : "=l"(d) : "l"(a), "l"(b), "l"(c)); return d;
}
__device__ __forceinline__ float2 upk(ull v) {
    float2 r; asm("mov.b64 {%0, %1}, %2;" : "=f"(r.x), "=f"(r.y) : "l"(v)); return r;
}
__device__ __forceinline__ float ex2f(float x) {
    float r; asm("ex2.approx.f32 %0, %1;" : "=f"(r) : "f"(x)); return r;
}
__device__ __forceinline__ unsigned pkh2(float a, float b) {
    __half2 h = __floats2half2_rn(a, b);
    return *reinterpret_cast<unsigned*>(&h);
}
__device__ __forceinline__ void stcs4(float* p, float4 v) {
    asm volatile("st.global.cs.v4.f32 [%0], {%1, %2, %3, %4};"
                 :: "l"(p), "f"(v.x), "f"(v.y), "f"(v.z), "f"(v.w) : "memory");
}
__device__ __forceinline__ ull ldg_nc64(const ull* p) {
    ull v; asm("ld.global.nc.b64 %0, [%1];" : "=l"(v) : "l"(p)); return v;
}

// ---- pre-kernel: transpose X into f-pair rows + cexp*||x_j||^2 ----
__global__ void __launch_bounds__(256)
prep_kernel(const float* __restrict__ X, const float* __restrict__ sigma) {
    int idx = blockIdx.x * 256 + threadIdx.x;          // b*4096 + j
    int b = idx >> 12, j = idx & 4095;
    const float4* p = reinterpret_cast<const float4*>(X) + (size_t)idx * 4;
    float s = 0.f;
    float2* xtb = reinterpret_cast<float2*>(&g_xt[b * 65536]) + j;
    #pragma unroll
    for (int q = 0; q < 4; ++q) {
        float4 v = p[q];
        s += v.x * v.x + v.y * v.y + v.z * v.z + v.w * v.w;
        xtb[(2 * q + 0) * 4096] = make_float2(v.x, v.y);
        xtb[(2 * q + 1) * 4096] = make_float2(v.z, v.w);
    }
    g_sqc[idx] = (-L2E / sigma[0]) * s;
}

__global__ void __launch_bounds__(TT, 2)
GaussianSoftmax_67714454389333_kernel(const float* __restrict__ X,
                                      const float* __restrict__ sigma,
                                      float* __restrict__ out) {
    extern __shared__ char smem_raw[];
    unsigned* hbuf = reinterpret_cast<unsigned*>(smem_raw + HBUF_OFF);  // [8][2048]

    const int tid = threadIdx.x;
    const int b = blockIdx.y;
    const int i0 = blockIdx.x * RR;

    const float* Xb = X + (size_t)b * NN * FF;

    const float sg = sigma[0];
    const float cexp = -L2E / sg;
    const float CM2s = -2.0f * cexp;

    // ---- xq: f-paired xi in regs for ALL 8 rows (128 regs) + sic ----
    ull xq[8][RR];
    float sic[RR];
    #pragma unroll
    for (int r = 0; r < RR; ++r) {
        float s = 0.f;
        #pragma unroll
        for (int fp = 0; fp < 8; ++fp) {
            float2 v = *reinterpret_cast<const float2*>(
                &Xb[(size_t)(i0 + r) * FF + fp * 2]);
            s = fmaf(v.x, v.x, s);
            s = fmaf(v.y, v.y, s);
            xq[fp][r] = *reinterpret_cast<const ull*>(&v);
        }
        sic[r] = fmaf(cexp, s, C528);
    }

    const ull* xt = reinterpret_cast<const ull*>(g_xt) + (size_t)b * 32768;
    const float* sq = g_sqc + b * NN;

    float rsum[RR];
    #pragma unroll
    for (int r = 0; r < RR; ++r) rsum[r] = 0.f;

    // ---- barrier-free mainloop: 16 k-steps x 2 cols (tid, tid+128) ----
    #pragma unroll 1
    for (int k = 0; k < NK; ++k) {
        const int jA = k * 256 + tid;      // col A; col B = jA + 128

        // coalesced read-only loads (L2-resident g_xt; lane-contiguous 256B/warp)
        ull xa[8], xb[8];
        #pragma unroll
        for (int fp = 0; fp < 8; ++fp) {
            xa[fp] = ldg_nc64(xt + fp * 4096 + jA);
            xb[fp] = ldg_nc64(xt + fp * 4096 + jA + 128);
        }
        float sjA = __ldg(sq + jA);
        float sjB = __ldg(sq + jA + 128);

        // dot products: 8 rows x 2 cols, f-paired lanes
        ull accA[RR], accB[RR];
        #pragma unroll
        for (int r = 0; r < RR; ++r) { accA[r] = 0; accB[r] = 0; }
        #pragma unroll
        for (int fp = 0; fp < 8; ++fp) {
            #pragma unroll
            for (int r = 0; r < RR; ++r) {
                accA[r] = ffma2(xa[fp], xq[fp][r], accA[r]);
                accB[r] = ffma2(xb[fp], xq[fp][r], accB[r]);
            }
        }

        // epilogue: e = CM2s*dot + sic + sj ; h = 2^(2^e); fp16 h to smem
        #pragma unroll
        for (int r = 0; r < RR; ++r) {
            float2 aA = upk(accA[r]);
            float2 aB = upk(accB[r]);
            float eA = fmaf(CM2s, aA.x + aA.y, sic[r] + sjA);
            float eB = fmaf(CM2s, aB.x + aB.y, sic[r] + sjB);
            float hA = ex2f(ex2f(eA));
            float hB = ex2f(ex2f(eB));
            rsum[r] += hA + hB;
            hbuf[r * 2048 + k * 128 + tid] = pkh2(hA, hB);   // (lo=col jA, hi=col jA+128)
        }
    }

    // ---- row-sum reduction (4 warps) ----
    float* part = reinterpret_cast<float*>(smem_raw + PART_OFF);   // [4][8]
    #pragma unroll
    for (int r = 0; r < RR; ++r) {
        float v = rsum[r];
        v += __shfl_xor_sync(0xffffffffu, v, 16);
        v += __shfl_xor_sync(0xffffffffu, v, 8);
        v += __shfl_xor_sync(0xffffffffu, v, 4);
        v += __shfl_xor_sync(0xffffffffu, v, 2);
        v += __shfl_xor_sync(0xffffffffu, v, 1);
        if ((tid & 31) == 0) part[(tid >> 5) * 8 + r] = v;
    }
    __syncthreads();
    float* invp = reinterpret_cast<float*>(smem_raw + INV_OFF);
    if (tid < RR) {
        float s = part[0 * 8 + tid] + part[1 * 8 + tid] +
                  part[2 * 8 + tid] + part[3 * 8 + tid];
        invp[tid] = 1.0f / s;
    }
    __syncthreads();

    // ---- phase 2: normalize fp16 h, two coalesced STG.128 per uint4 ----
    float* outB = out + ((size_t)b * NN + i0) * NN;
    const uint4* h4 = reinterpret_cast<const uint4*>(hbuf);        // [8][512]
    #pragma unroll 4
    for (int it = 0; it < 32; ++it) {
        int c4 = it * TT + tid;          // 0..4095
        int r = c4 >> 9;
        int w = c4 & 511;
        int kk = w >> 5;
        int a = w & 31;
        float inv = invp[r];
        uint4 v = h4[c4];
        float2 p0 = __half22float2(*reinterpret_cast<__half2*>(&v.x));
        float2 p1 = __half22float2(*reinterpret_cast<__half2*>(&v.y));
        float2 p2 = __half22float2(*reinterpret_cast<__half2*>(&v.z));
        float2 p3 = __half22float2(*reinterpret_cast<__half2*>(&v.w));
        float4 oA = make_float4(p0.x * inv, p1.x * inv, p2.x * inv, p3.x * inv);
        float4 oB = make_float4(p0.y * inv, p1.y * inv, p2.y * inv, p3.y * inv);
        float* po = outB + (size_t)r * NN + kk * 256 + a * 4;
        stcs4(po, oA);
        stcs4(po + 128, oB);
    }
}

extern "C" void kernel_launch(void* const* d_in, const int* in_sizes, int n_in,
                              void* d_out, int out_size) {
    const float* X = (const float*)d_in[0];
    const float* sigma = (const float*)d_in[1];
    float* out = (float*)d_out;

    prep_kernel<<<BB * NN / 256, 256>>>(X, sigma);

    cudaFuncSetAttribute(GaussianSoftmax_67714454389333_kernel,
                         cudaFuncAttributeMaxDynamicSharedMemorySize, SMEM_TOTAL);
    dim3 grid(NN / RR, BB);   // (512, 8)
    GaussianSoftmax_67714454389333_kernel<<<grid, TT, SMEM_TOTAL>>>(X, sigma, out);
}